// round 13
// baseline (speedup 1.0000x reference)
#include <cuda_runtime.h>
#include <cuda_fp16.h>
#include <math.h>
#include <stdint.h>

#define BATCH 8
#define SEQ 1900
#define SEQP 1904
#define EMB 256
#define NHEAD 8
#define HDIM 32
#define NTOK (BATCH*SEQ)       // 15200
#define F3 (3*EMB)             // 768
#define PADSZ 1000
#define GROUPSZ 200
#define LNEPS 1e-5f
#define QP 20                  // smem pitch (u32 words)

// ---------------- scratch (device globals, no allocations) ----------------
__device__ __align__(16) uint32_t g_xh [NTOK*128];
__device__ __align__(16) uint32_t g_wih[F3*128];
__device__ __align__(16) uint32_t g_woh[EMB*128];
__device__ __align__(16) uint32_t g_qh [BATCH*NHEAD*SEQ*16];
__device__ __align__(16) uint32_t g_kh [BATCH*NHEAD*SEQ*16];
__device__ __align__(16) __half   g_vt [BATCH*NHEAD*HDIM*SEQP];
__device__ __align__(16) uint32_t g_ctxh[NTOK*128];

__device__ __forceinline__ float fast_exp2(float x) {
    float y;
    asm("ex2.approx.ftz.f32 %0, %1;" : "=f"(y) : "f"(x));
    return y;
}
__device__ __forceinline__ uint32_t h2pack(float a, float b) {
    __half2 h = __floats2half2_rn(a, b);
    return *(uint32_t*)&h;
}
__device__ __forceinline__ void mma_f16(float& c0, float& c1, float& c2, float& c3,
                                        uint32_t a0, uint32_t a1, uint32_t a2, uint32_t a3,
                                        uint32_t b0, uint32_t b1) {
    asm volatile(
        "mma.sync.aligned.m16n8k16.row.col.f32.f16.f16.f32 "
        "{%0,%1,%2,%3}, {%4,%5,%6,%7}, {%8,%9}, {%0,%1,%2,%3};"
        : "+f"(c0), "+f"(c1), "+f"(c2), "+f"(c3)
        : "r"(a0), "r"(a1), "r"(a2), "r"(a3), "r"(b0), "r"(b1));
}
__device__ __forceinline__ void cp_async16(uint32_t smem_addr, const void* gsrc, uint32_t src_bytes) {
    asm volatile("cp.async.cg.shared.global [%0], [%1], 16, %2;\n"
                 :: "r"(smem_addr), "l"(gsrc), "r"(src_bytes));
}
__device__ __forceinline__ void cp_commit() {
    asm volatile("cp.async.commit_group;\n");
}
template <int N>
__device__ __forceinline__ void cp_wait() {
    asm volatile("cp.async.wait_group %0;\n" :: "n"(N));
}

// ===========================================================================
// Kernel 0: fp32 -> fp16 conversion
// ===========================================================================
#define NX4  (NTOK*64)
#define NWI4 (F3*64)
#define NWO4 (EMB*64)
__global__ __launch_bounds__(256) void cvt_kernel(
    const float* __restrict__ x,
    const float* __restrict__ wi,
    const float* __restrict__ wo)
{
    int i = blockIdx.x * blockDim.x + threadIdx.x;
    float4 v;
    uint2* dst;
    if (i < NX4)                 { v = ((const float4*)x)[i];  dst = (uint2*)g_xh + i; }
    else if (i < NX4 + NWI4)     { int j = i - NX4;  v = ((const float4*)wi)[j]; dst = (uint2*)g_wih + j; }
    else if (i < NX4 + NWI4 + NWO4) { int j = i - NX4 - NWI4; v = ((const float4*)wo)[j]; dst = (uint2*)g_woh + j; }
    else return;
    uint2 r;
    r.x = h2pack(v.x, v.y);
    r.y = h2pack(v.z, v.w);
    *dst = r;
}

// ===========================================================================
// Kernel 1: QKV (fp16 MMA). 256 threads / 8 warps, BM=128 BN=64 BK=32, 3-stage.
// Warp w computes rows [16w,16w+16) x 64 cols; C[8][4] = 32 regs.
// ===========================================================================
__global__ __launch_bounds__(256, 3) void qkv_h_kernel(const float* __restrict__ bias)
{
    __shared__ __align__(16) uint32_t As[3 * 128 * QP];
    __shared__ __align__(16) uint32_t Bs[3 * 64 * QP];

    const int n0 = blockIdx.x * 128;
    const int f0 = blockIdx.y * 64;
    const int tid = threadIdx.x;
    const int wid = tid >> 5;
    const int lane = tid & 31;
    const int g = lane >> 2;
    const int t = lane & 3;
    const int rw = 16 * wid;

    float C[8][4];
#pragma unroll
    for (int nn = 0; nn < 8; nn++)
#pragma unroll
        for (int e = 0; e < 4; e++) C[nn][e] = 0.f;

    const uint32_t as_base = (uint32_t)__cvta_generic_to_shared(As);
    const uint32_t bs_base = (uint32_t)__cvta_generic_to_shared(Bs);

    auto load_stage = [&](int kc, int st) {
        int k0 = kc * 16;
        uint32_t a_st = as_base + st * (128 * QP) * 4;
        uint32_t b_st = bs_base + st * (64 * QP) * 4;
        // A: 128 rows x 4 chunks = 512 tasks, 2/thread
#pragma unroll
        for (int i = 0; i < 2; i++) {
            int idx = tid + i * 256;
            int row = idx >> 2;
            int ch  = idx & 3;
            int gn = n0 + row;
            bool ok = (gn < NTOK);
            cp_async16(a_st + (row * QP + ch * 4) * 4,
                       g_xh + (size_t)(ok ? gn : 0) * 128 + k0 + ch * 4, ok ? 16u : 0u);
        }
        // B: 64 rows x 4 chunks = 256 tasks, 1/thread
        {
            int row = tid >> 2;
            int ch  = tid & 3;
            cp_async16(b_st + (row * QP + ch * 4) * 4,
                       g_wih + (size_t)(f0 + row) * 128 + k0 + ch * 4, 16u);
        }
        cp_commit();
    };

    load_stage(0, 0);
    load_stage(1, 1);

    for (int kc = 0; kc < 8; kc++) {
        __syncthreads();
        if (kc + 2 < 8) { load_stage(kc + 2, (kc + 2) % 3); cp_wait<2>(); }
        else if (kc + 1 < 8) { cp_wait<1>(); }
        else { cp_wait<0>(); }
        __syncthreads();

        const uint32_t* as = As + (kc % 3) * (128 * QP);
        const uint32_t* bs = Bs + (kc % 3) * (64 * QP);

#pragma unroll
        for (int s = 0; s < 2; s++) {
            int wl = 8 * s + t;
            int wh = wl + 4;
            uint32_t a0 = as[(rw + g)     * QP + wl];
            uint32_t a1 = as[(rw + g + 8) * QP + wl];
            uint32_t a2 = as[(rw + g)     * QP + wh];
            uint32_t a3 = as[(rw + g + 8) * QP + wh];
#pragma unroll
            for (int nn = 0; nn < 8; nn++) {
                int fr = 8 * nn + g;
                uint32_t b0 = bs[fr * QP + wl];
                uint32_t b1 = bs[fr * QP + wh];
                mma_f16(C[nn][0], C[nn][1], C[nn][2], C[nn][3],
                        a0, a1, a2, a3, b0, b1);
            }
        }
    }

    const float QS = 0.17677669529663687f * 1.4426950408889634f;

#pragma unroll
    for (int half = 0; half < 2; half++) {
        int n = n0 + rw + 8 * half + g;
        if (n >= NTOK) continue;
        int b = n / SEQ;
        int l = n % SEQ;
#pragma unroll
        for (int nn = 0; nn < 8; nn++) {
            int f = f0 + 8 * nn + 2 * t;
            float v0 = C[nn][2 * half]     + bias[f];
            float v1 = C[nn][2 * half + 1] + bias[f + 1];
            int which = f >> 8;
            int e = f & 255;
            int h = e >> 5;
            int d = e & 31;
            int bh = b * NHEAD + h;
            if (which == 0) {
                g_qh[((size_t)bh * SEQ + l) * 16 + (d >> 1)] = h2pack(v0 * QS, v1 * QS);
            } else if (which == 1) {
                g_kh[((size_t)bh * SEQ + l) * 16 + (d >> 1)] = h2pack(v0, v1);
            } else {
                g_vt[((size_t)bh * HDIM + d)     * SEQP + l] = __float2half(v0);
                g_vt[((size_t)bh * HDIM + d + 1) * SEQP + l] = __float2half(v1);
            }
        }
    }
}

// ===========================================================================
// Kernel 2: flash attention fp16. half2 exp2; lsum via paired HADD2 + f32
// flush (ones-column removed: PV = 16 MMAs/tile); mask-free interior path.
// ===========================================================================
__global__ __launch_bounds__(256) void attn_f16_kernel()
{
    const int bh  = blockIdx.y;
    const int l0  = blockIdx.x * 128;
    const int tid = threadIdx.x;
    const int wid = tid >> 5;
    const int lane = tid & 31;
    const int g = lane >> 2;
    const int t = lane & 3;
    const int r_lo = l0 + wid * 16 + g;
    const int r_hi = r_lo + 8;

    __shared__ __align__(16) uint32_t Ks[2 * 64 * 20];
    __shared__ __align__(16) uint32_t Vts[2 * 32 * 32];

    const uint32_t ks_base = (uint32_t)__cvta_generic_to_shared(Ks);
    const uint32_t vt_base = (uint32_t)__cvta_generic_to_shared(Vts);

    const uint32_t* qw = g_qh + (size_t)bh * SEQ * 16;
    uint32_t Aq[2][4];
#pragma unroll
    for (int s = 0; s < 2; s++) {
        Aq[s][0] = Aq[s][1] = Aq[s][2] = Aq[s][3] = 0;
        if (r_lo < SEQ) {
            Aq[s][0] = qw[(size_t)r_lo * 16 + t + 8 * s];
            Aq[s][2] = qw[(size_t)r_lo * 16 + t + 4 + 8 * s];
        }
        if (r_hi < SEQ) {
            Aq[s][1] = qw[(size_t)r_hi * 16 + t + 8 * s];
            Aq[s][3] = qw[(size_t)r_hi * 16 + t + 4 + 8 * s];
        }
    }

    float o[4][4];
#pragma unroll
    for (int nn = 0; nn < 4; nn++)
#pragma unroll
        for (int e = 0; e < 4; e++) o[nn][e] = 0.f;

    float m_lo = -INFINITY, m_hi = -INFINITY;
    float l_lo = 0.f, l_hi = 0.f;

    const int glo = (r_lo < PADSZ) ? (r_lo / GROUPSZ) : -1;
    const int ghi = (r_hi < PADSZ) ? (r_hi / GROUPSZ) : -1;
    const bool blk_has_pad = (l0 < PADSZ);
    const int gminb = l0 / GROUPSZ;
    const int gmaxb = (min(l0 + 127, PADSZ - 1)) / GROUPSZ;

    auto tile_needed = [&](int m0) -> bool {
        if (m0 + 64 > PADSZ) return true;
        if (!blk_has_pad) return false;
        int gt0 = m0 / GROUPSZ, gt1 = (m0 + 63) / GROUPSZ;
        return !(gmaxb < gt0 || gminb > gt1);
    };

    const int k_row = tid >> 2;
    const int k_ch  = tid & 3;
    const int v_d   = tid >> 3;
    const int v_ch  = tid & 7;
    const uint32_t* kbh = g_kh + (size_t)bh * SEQ * 16;
    const __half*   vbh = g_vt + (size_t)bh * HDIM * SEQP;

    auto load_tile = [&](int m0, int buf) {
        uint32_t k_dst = ks_base + (buf * (64 * 20) + k_row * 20 + k_ch * 4) * 4;
        uint32_t v_dst = vt_base + (buf * (32 * 32) + v_d * 32 + ((v_ch * 4) ^ ((v_d & 7) << 2))) * 4;
        int m = m0 + k_row;
        cp_async16(k_dst, kbh + (size_t)(m < SEQ ? m : 0) * 16 + k_ch * 4,
                   (m < SEQ) ? 16u : 0u);
        int ms = m0 + v_ch * 8;
        uint32_t nb = 0;
        if (ms < SEQ) { int rem = (SEQ - ms) * 2; nb = rem >= 16 ? 16u : (uint32_t)rem; }
        cp_async16(v_dst, vbh + (size_t)v_d * SEQP + ms, nb);
        cp_commit();
    };

    int m0 = 0;
    while (m0 < SEQ && !tile_needed(m0)) m0 += 64;
    if (m0 < SEQ) load_tile(m0, 0);
    int buf = 0;

    while (m0 < SEQ) {
        int mn = m0 + 64;
        while (mn < SEQ && !tile_needed(mn)) mn += 64;

        __syncthreads();
        if (mn < SEQ) { load_tile(mn, buf ^ 1); cp_wait<1>(); }
        else          { cp_wait<0>(); }
        __syncthreads();

        const uint32_t* ks = Ks + buf * (64 * 20);
        const uint32_t* vs = Vts + buf * (32 * 32);

        // --- scores S = Q @ K^T ---
        float S[8][4];
#pragma unroll
        for (int j = 0; j < 8; j++) {
            S[j][0] = 0.f; S[j][1] = 0.f; S[j][2] = 0.f; S[j][3] = 0.f;
            int kb = (8 * j + g) * 20;
#pragma unroll
            for (int s = 0; s < 2; s++) {
                uint32_t b0 = ks[kb + t + 8 * s];
                uint32_t b1 = ks[kb + t + 4 + 8 * s];
                mma_f16(S[j][0], S[j][1], S[j][2], S[j][3],
                        Aq[s][0], Aq[s][1], Aq[s][2], Aq[s][3], b0, b1);
            }
        }

        // --- mask (only when needed) + rowmax ---
        const bool domask = (m0 < PADSZ) || (m0 + 64 > SEQ);
        float tmax_lo = -INFINITY, tmax_hi = -INFINITY;
        if (domask) {
#pragma unroll
            for (int j = 0; j < 8; j++) {
                int c0 = m0 + 8 * j + 2 * t;
                int c1 = c0 + 1;
                int mg0 = c0 / GROUPSZ;
                int mg1 = c1 / GROUPSZ;
                bool b0lo = (c0 >= SEQ) || (c0 < PADSZ && mg0 != glo);
                bool b1lo = (c1 >= SEQ) || (c1 < PADSZ && mg1 != glo);
                bool b0hi = (c0 >= SEQ) || (c0 < PADSZ && mg0 != ghi);
                bool b1hi = (c1 >= SEQ) || (c1 < PADSZ && mg1 != ghi);
                if (b0lo) S[j][0] = -INFINITY;
                if (b1lo) S[j][1] = -INFINITY;
                if (b0hi) S[j][2] = -INFINITY;
                if (b1hi) S[j][3] = -INFINITY;
                tmax_lo = fmaxf(tmax_lo, fmaxf(S[j][0], S[j][1]));
                tmax_hi = fmaxf(tmax_hi, fmaxf(S[j][2], S[j][3]));
            }
        } else {
#pragma unroll
            for (int j = 0; j < 8; j++) {
                tmax_lo = fmaxf(tmax_lo, fmaxf(S[j][0], S[j][1]));
                tmax_hi = fmaxf(tmax_hi, fmaxf(S[j][2], S[j][3]));
            }
        }
        tmax_lo = fmaxf(tmax_lo, __shfl_xor_sync(0xffffffffu, tmax_lo, 1));
        tmax_lo = fmaxf(tmax_lo, __shfl_xor_sync(0xffffffffu, tmax_lo, 2));
        tmax_hi = fmaxf(tmax_hi, __shfl_xor_sync(0xffffffffu, tmax_hi, 1));
        tmax_hi = fmaxf(tmax_hi, __shfl_xor_sync(0xffffffffu, tmax_hi, 2));

        float mnew_lo = fmaxf(m_lo, tmax_lo);
        float mnew_hi = fmaxf(m_hi, tmax_hi);
        float msafe_lo = (mnew_lo == -INFINITY) ? 0.f : mnew_lo;
        float msafe_hi = (mnew_hi == -INFINITY) ? 0.f : mnew_hi;
        float corr_lo = fast_exp2(m_lo - msafe_lo);
        float corr_hi = fast_exp2(m_hi - msafe_hi);
        m_lo = mnew_lo; m_hi = mnew_hi;

#pragma unroll
        for (int nn = 0; nn < 4; nn++) {
            o[nn][0] *= corr_lo; o[nn][1] *= corr_lo;
            o[nn][2] *= corr_hi; o[nn][3] *= corr_hi;
        }

        // --- P = exp2(S - m) in half2 (directly the PV A-fragments) ---
        uint32_t P01[8], P23[8];
#pragma unroll
        for (int j = 0; j < 8; j++) {
            uint32_t s01, s23;
            asm("cvt.rn.f16x2.f32 %0, %1, %2;" : "=r"(s01)
                : "f"(S[j][1] - msafe_lo), "f"(S[j][0] - msafe_lo));
            asm("cvt.rn.f16x2.f32 %0, %1, %2;" : "=r"(s23)
                : "f"(S[j][3] - msafe_hi), "f"(S[j][2] - msafe_hi));
            asm("ex2.approx.f16x2 %0, %1;" : "=r"(P01[j]) : "r"(s01));
            asm("ex2.approx.f16x2 %0, %1;" : "=r"(P23[j]) : "r"(s23));
        }

        // --- lsum: paired HADD2 then f32 flush (no ones-column) ---
        float tl_lo = 0.f, tl_hi = 0.f;
#pragma unroll
        for (int j = 0; j < 8; j += 2) {
            __half2 plo = __hadd2(*(const __half2*)&P01[j], *(const __half2*)&P01[j + 1]);
            __half2 phi = __hadd2(*(const __half2*)&P23[j], *(const __half2*)&P23[j + 1]);
            float2 flo = __half22float2(plo);
            float2 fhi = __half22float2(phi);
            tl_lo += flo.x + flo.y;
            tl_hi += fhi.x + fhi.y;
        }
        l_lo = l_lo * corr_lo + tl_lo;
        l_hi = l_hi * corr_hi + tl_hi;

        // --- PV: 16 MMAs ---
#pragma unroll
        for (int c = 0; c < 4; c++) {
            uint32_t pa0 = P01[2 * c];
            uint32_t pa1 = P23[2 * c];
            uint32_t pa2 = P01[2 * c + 1];
            uint32_t pa3 = P23[2 * c + 1];
#pragma unroll
            for (int nn = 0; nn < 4; nn++) {
                int vr = (8 * nn + g) * 32;
                uint32_t b0 = vs[vr + ((8 * c + t)     ^ (g << 2))];
                uint32_t b1 = vs[vr + ((8 * c + t + 4) ^ (g << 2))];
                mma_f16(o[nn][0], o[nn][1], o[nn][2], o[nn][3],
                        pa0, pa1, pa2, pa3, b0, b1);
            }
        }

        buf ^= 1;
        m0 = mn;
    }

    // quad-reduce row sums, normalize, store fp16 ctx
    l_lo += __shfl_xor_sync(0xffffffffu, l_lo, 1);
    l_lo += __shfl_xor_sync(0xffffffffu, l_lo, 2);
    l_hi += __shfl_xor_sync(0xffffffffu, l_hi, 1);
    l_hi += __shfl_xor_sync(0xffffffffu, l_hi, 2);
    float inv_lo = 1.0f / l_lo;
    float inv_hi = 1.0f / l_hi;

    const int b = bh >> 3;
    const int h = bh & 7;
    if (r_lo < SEQ) {
        uint32_t* dst = &g_ctxh[((size_t)b * SEQ + r_lo) * 128 + h * 16];
#pragma unroll
        for (int nn = 0; nn < 4; nn++)
            dst[4 * nn + t] = h2pack(o[nn][0] * inv_lo, o[nn][1] * inv_lo);
    }
    if (r_hi < SEQ) {
        uint32_t* dst = &g_ctxh[((size_t)b * SEQ + r_hi) * 128 + h * 16];
#pragma unroll
        for (int nn = 0; nn < 4; nn++)
            dst[4 * nn + t] = h2pack(o[nn][2] * inv_hi, o[nn][3] * inv_hi);
    }
}

// ===========================================================================
// Kernel 3: fused out = LN(x + ctx @ out_w^T + out_b)
// BM=64, BN=256, BK=32 fp16, 256 threads, forced 2 blocks/SM
// ===========================================================================
__device__ __forceinline__ int swz16(int r) { return ((r >> 1) & 3) << 2; }

__global__ __launch_bounds__(256, 2) void out_ln_kernel(
    const float* __restrict__ x,
    const float* __restrict__ bias,
    const float* __restrict__ gamma,
    const float* __restrict__ beta,
    float* __restrict__ out)
{
    __shared__ __align__(16) uint32_t As[2 * 64 * 16];
    __shared__ __align__(16) uint32_t Bs[2 * 256 * 16];
    __shared__ float s_sum[64][4];
    __shared__ float s_sqs[64][4];

    const int n0 = blockIdx.x * 64;
    const int tid = threadIdx.x;
    const int wid = tid >> 5;
    const int lane = tid & 31;
    const int g = lane >> 2;
    const int t = lane & 3;
    const int band = wid >> 2;
    const int quad = wid & 3;

    float C[8][2][4];
#pragma unroll
    for (int nn = 0; nn < 8; nn++)
#pragma unroll
        for (int b = 0; b < 2; b++)
#pragma unroll
            for (int e = 0; e < 4; e++) C[nn][b][e] = 0.f;

    const uint32_t as_base = (uint32_t)__cvta_generic_to_shared(As);
    const uint32_t bs_base = (uint32_t)__cvta_generic_to_shared(Bs);

    auto load_stage = [&](int kc, int st) {
        int k0 = kc * 16;
        uint32_t a_st = as_base + st * (64 * 16) * 4;
        uint32_t b_st = bs_base + st * (256 * 16) * 4;
        {
            int row = tid >> 2;
            int ch  = tid & 3;
            int gn = n0 + row;
            bool ok = (gn < NTOK);
            cp_async16(a_st + (row * 16 + ((ch * 4) ^ swz16(row))) * 4,
                       g_ctxh + (size_t)(ok ? gn : 0) * 128 + k0 + ch * 4, ok ? 16u : 0u);
        }
#pragma unroll
        for (int i = 0; i < 4; i++) {
            int idx = tid + i * 256;
            int row = idx >> 2;
            int ch  = idx & 3;
            cp_async16(b_st + (row * 16 + ((ch * 4) ^ swz16(row))) * 4,
                       g_woh + (size_t)row * 128 + k0 + ch * 4, 16u);
        }
        cp_commit();
    };

    load_stage(0, 0);

    const int Rb = 32 * band;
    const int sA = swz16(g);

    for (int kc = 0; kc < 8; kc++) {
        __syncthreads();
        if (kc + 1 < 8) { load_stage(kc + 1, (kc + 1) & 1); cp_wait<1>(); }
        else            { cp_wait<0>(); }
        __syncthreads();

        const uint32_t* as = As + (kc & 1) * (64 * 16);
        const uint32_t* bs = Bs + (kc & 1) * (256 * 16);

#pragma unroll
        for (int s = 0; s < 2; s++) {
            int wl = (8 * s + t) ^ sA;
            int wh = (8 * s + t + 4) ^ sA;
            uint32_t a00 = as[(Rb + g)      * 16 + wl];
            uint32_t a01 = as[(Rb + g + 8)  * 16 + wl];
            uint32_t a02 = as[(Rb + g)      * 16 + wh];
            uint32_t a03 = as[(Rb + g + 8)  * 16 + wh];
            uint32_t a10 = as[(Rb + g + 16) * 16 + wl];
            uint32_t a11 = as[(Rb + g + 24) * 16 + wl];
            uint32_t a12 = as[(Rb + g + 16) * 16 + wh];
            uint32_t a13 = as[(Rb + g + 24) * 16 + wh];
#pragma unroll
            for (int nn = 0; nn < 8; nn++) {
                int fr = 64 * quad + 8 * nn + g;
                int wbl = (8 * s + t) ^ swz16(fr);
                int wbh = (8 * s + t + 4) ^ swz16(fr);
                uint32_t b0 = bs[fr * 16 + wbl];
                uint32_t b1 = bs[fr * 16 + wbh];
                mma_f16(C[nn][0][0], C[nn][0][1], C[nn][0][2], C[nn][0][3],
                        a00, a01, a02, a03, b0, b1);
                mma_f16(C[nn][1][0], C[nn][1][1], C[nn][1][2], C[nn][1][3],
                        a10, a11, a12, a13, b0, b1);
            }
        }
    }

    const int r0 = n0 + Rb + g;
    float sum[4] = {0.f, 0.f, 0.f, 0.f};
    float sqs[4] = {0.f, 0.f, 0.f, 0.f};
#pragma unroll
    for (int nn = 0; nn < 8; nn++) {
        int f = 64 * quad + 8 * nn + 2 * t;
        float b0 = bias[f], b1 = bias[f + 1];
#pragma unroll
        for (int blk = 0; blk < 2; blk++) {
#pragma unroll
            for (int half = 0; half < 2; half++) {
                int r = r0 + 16 * blk + 8 * half;
                int e0 = 2 * half, e1 = e0 + 1;
                if (r < NTOK) {
                    float2 xr = *(const float2*)&x[(size_t)r * 256 + f];
                    C[nn][blk][e0] += b0 + xr.x;
                    C[nn][blk][e1] += b1 + xr.y;
                }
                int ridx = 2 * blk + half;
                sum[ridx] += C[nn][blk][e0] + C[nn][blk][e1];
                sqs[ridx] += C[nn][blk][e0] * C[nn][blk][e0] + C[nn][blk][e1] * C[nn][blk][e1];
            }
        }
    }
#pragma unroll
    for (int ridx = 0; ridx < 4; ridx++) {
        sum[ridx] += __shfl_xor_sync(0xffffffffu, sum[ridx], 1);
        sum[ridx] += __shfl_xor_sync(0xffffffffu, sum[ridx], 2);
        sqs[ridx] += __shfl_xor_sync(0xffffffffu, sqs[ridx], 1);
        sqs[ridx] += __shfl_xor_sync(0xffffffffu, sqs[ridx], 2);
    }
    if (t == 0) {
#pragma unroll
        for (int ridx = 0; ridx < 4; ridx++) {
            s_sum[Rb + g + 8 * ridx][quad] = sum[ridx];
            s_sqs[Rb + g + 8 * ridx][quad] = sqs[ridx];
        }
    }
    __syncthreads();

    float mean[4], rs[4];
#pragma unroll
    for (int ridx = 0; ridx < 4; ridx++) {
        int sr = Rb + g + 8 * ridx;
        float S1 = s_sum[sr][0] + s_sum[sr][1] + s_sum[sr][2] + s_sum[sr][3];
        float S2 = s_sqs[sr][0] + s_sqs[sr][1] + s_sqs[sr][2] + s_sqs[sr][3];
        mean[ridx] = S1 * (1.0f / 256.0f);
        float var = S2 * (1.0f / 256.0f) - mean[ridx] * mean[ridx];
        rs[ridx] = rsqrtf(var + LNEPS);
    }

#pragma unroll
    for (int nn = 0; nn < 8; nn++) {
        int f = 64 * quad + 8 * nn + 2 * t;
        float gm0 = gamma[f], gm1 = gamma[f + 1];
        float bt0 = beta[f],  bt1 = beta[f + 1];
#pragma unroll
        for (int blk = 0; blk < 2; blk++) {
#pragma unroll
            for (int half = 0; half < 2; half++) {
                int r = r0 + 16 * blk + 8 * half;
                if (r >= NTOK) continue;
                int ridx = 2 * blk + half;
                int e0 = 2 * half;
                float2 w;
                w.x = (C[nn][blk][e0]     - mean[ridx]) * rs[ridx] * gm0 + bt0;
                w.y = (C[nn][blk][e0 + 1] - mean[ridx]) * rs[ridx] * gm1 + bt1;
                *(float2*)&out[(size_t)r * 256 + f] = w;
            }
        }
    }
}

// ---------------------------------------------------------------------------
extern "C" void kernel_launch(void* const* d_in, const int* in_sizes, int n_in,
                              void* d_out, int out_size)
{
    const float* x     = (const float*)d_in[0];
    const float* in_w  = (const float*)d_in[1];
    const float* in_b  = (const float*)d_in[2];
    const float* out_w = (const float*)d_in[3];
    const float* out_b = (const float*)d_in[4];
    const float* ln_g  = (const float*)d_in[5];
    const float* ln_b  = (const float*)d_in[6];
    float* out = (float*)d_out;

    cvt_kernel<<<(NX4 + NWI4 + NWO4 + 255) / 256, 256>>>(x, in_w, out_w);
    qkv_h_kernel<<<dim3((NTOK + 127) / 128, F3 / 64), 256>>>(in_b);
    attn_f16_kernel<<<dim3((SEQ + 127) / 128, BATCH * NHEAD), 256>>>();
    out_ln_kernel<<<(NTOK + 63) / 64, 256>>>(x, out_b, ln_g, ln_b, out);
}